// round 8
// baseline (speedup 1.0000x reference)
#include <cuda_runtime.h>
#include <cstdint>

// out4[((b*H+y)*W+x)*768 + ch*4 + i] = float4{ in[b,ch,y+i-3, x-2..x+1] },
// zero-padded; lanes z,w zeroed when i==3. B=8, C=192, H=W=48.
// Block = (b, y, 8-wide x-tile). Smem: [768 chi-rows][16 words], XOR-swizzled
// at float4 granularity -> conflict-free LDS.128 and cp.async STS.

#define B_   8
#define C_   192
#define H_   48
#define W_   48
#define TX   8
#define XT   (W_ / TX)             // 6
#define SROWS (C_ * 4)             // 768 chi rows
#define SELEMS (SROWS * 16)        // 12288 floats = 49152 B (4 CTAs/SM)

__device__ __forceinline__ void cp_async16(uint32_t saddr, const float* gaddr, bool valid)
{
    const int sz = valid ? 16 : 0;   // src_size=0 -> zero-fill, no global read
    asm volatile("cp.async.cg.shared.global [%0], [%1], 16, %2;\n"
                 :: "r"(saddr), "l"(gaddr), "r"(sz));
}

__global__ void __launch_bounds__(256)
block_sample_smem(const float* __restrict__ in, float4* __restrict__ out)
{
    __shared__ float s[SELEMS];

    const int tid = threadIdx.x;
    int bid = blockIdx.x;
    const int xt = bid % XT;  bid /= XT;
    const int y  = bid % H_;
    const int b  = bid / H_;
    const int x0 = xt * TX;

    const uint32_t sbase = (uint32_t)__cvta_generic_to_shared(s);

    // ---- fill: per (chi, q) one 16B chunk, cols x0-4+4q .. +3, rows y-3..y ----
    // chunks are always fully in-bounds or fully out-of-bounds.
    #pragma unroll
    for (int k = 0; k < 12; k++) {                // 768 rows * 4 chunks / 256 thr
        const int idx = k * 256 + tid;
        const int q   = idx & 3;                  // float4 slot
        const int chi = idx >> 2;                 // ch*4 + r
        const int gy  = y + (chi & 3) - 3;        // <= 47 always
        const int c0  = x0 - 4 + (q << 2);        // -4 .. 44 (or 48 -> OOB)
        const bool ok = (gy >= 0) & (c0 >= 0) & (c0 < W_);
        const int gyc = ok ? gy : 0;
        const int c0c = ok ? c0 : 0;
        const float* g = in + ((b * C_ + (chi >> 2)) * H_ + gyc) * W_ + c0c;
        const uint32_t sl = (uint32_t)(q ^ ((chi >> 1) & 3));   // swizzled slot
        cp_async16(sbase + (uint32_t)chi * 64u + (sl << 4), g, ok);
    }
    asm volatile("cp.async.commit_group;\n" ::: "memory");
    asm volatile("cp.async.wait_group 0;\n" ::: "memory");
    __syncthreads();

    // ---- store: per chi read 16-word row via 4 conflict-free LDS.128,
    //      emit 8 sliding, coalesced streaming STG.128 ----
    float4* const obase = out + (long)((b * H_ + y) * W_ + x0) * SROWS;
    #pragma unroll
    for (int sub = 0; sub < 3; sub++) {           // 768 = 3*256
        const int chi = sub * 256 + tid;
        const int v   = (chi >> 1) & 3;
        const bool msk = (chi & 3) == 3;          // i == 3 -> mask z,w lanes
        const float4* srow = reinterpret_cast<const float4*>(s) + chi * 4;

        float w[16];
        const float4 f0 = srow[0 ^ v];
        const float4 f1 = srow[1 ^ v];
        const float4 f2 = srow[2 ^ v];
        const float4 f3 = srow[3 ^ v];
        w[0]=f0.x; w[1]=f0.y; w[2]=f0.z; w[3]=f0.w;
        w[4]=f1.x; w[5]=f1.y; w[6]=f1.z; w[7]=f1.w;
        w[8]=f2.x; w[9]=f2.y; w[10]=f2.z; w[11]=f2.w;
        w[12]=f3.x; w[13]=f3.y; w[14]=f3.z; w[15]=f3.w;

        float wm[13];
        #pragma unroll
        for (int c = 4; c < 13; c++) wm[c - 4] = msk ? 0.f : w[c];

        float4* o = obase + chi;
        #pragma unroll
        for (int xl = 0; xl < TX; xl++) {
            // output col window: x0+xl-2 .. x0+xl+1  -> local words 2+xl .. 5+xl
            __stcs(o + xl * SROWS,
                   make_float4(w[2 + xl], w[3 + xl], wm[xl], wm[xl + 1]));
        }
    }
}

extern "C" void kernel_launch(void* const* d_in, const int* in_sizes, int n_in,
                              void* d_out, int out_size)
{
    const float* in  = (const float*)d_in[0];
    float4*      out = (float4*)d_out;

    const int blocks = B_ * H_ * XT;   // 2304
    block_sample_smem<<<blocks, 256>>>(in, out);
}

// round 9
// speedup vs baseline: 1.0047x; 1.0047x over previous
#include <cuda_runtime.h>

// out4[((b*H+y)*W+x)*768 + ch*4 + i] = float4{ in[b,ch,y+i-3, x-2..x+1] },
// zero-padded; lanes z,w zeroed when i==3. B=8, C=192, H=W=48.
// Block = (b, y, 8-wide x-tile). Smem: [768 chi-rows][pitch 11] = 33792 B.

#define B_   8
#define C_   192
#define H_   48
#define W_   48
#define TX   8
#define XT   (W_ / TX)             // 6
#define PITCH 11                   // cols x0-2 .. x0+8 ; gcd(11,32)=1
#define SELEMS (C_ * 4 * PITCH)    // 8448 floats = 33792 B (6 CTAs/SM)
#define LOAD_ITERS (SELEMS / 256)  // 33

__global__ void __launch_bounds__(256, 6)
block_sample_smem(const float* __restrict__ in, float4* __restrict__ out)
{
    __shared__ float s[SELEMS];

    const int tid = threadIdx.x;
    int bid = blockIdx.x;
    const int xt = bid % XT;  bid /= XT;
    const int y  = bid % H_;
    const int b  = bid / H_;
    const int x0 = xt * TX;

    // ---- load: rows y-3..y, cols x0-2..x0+8, all 192 channels ----
    #pragma unroll 11
    for (int k = 0; k < LOAD_ITERS; k++) {
        const int idx = k * 256 + tid;
        const int sc  = idx % PITCH;       // 0..10
        const int rf  = idx / PITCH;       // ch*4 + r
        const int gy  = y + (rf & 3) - 3;  // <= 47 always
        const int gx  = x0 - 2 + sc;       // -2 .. 48
        float v = 0.f;
        if (gy >= 0 && gx >= 0 && gx < W_)
            v = __ldg(in + ((b * C_ + (rf >> 2)) * H_ + gy) * W_ + gx);
        s[idx] = v;
    }
    __syncthreads();

    // ---- store: per chi read 11-word window (conflict-free scalar LDS),
    //      emit 8 independent, coalesced streaming STG.128 ----
    float4* const obase = out + (long)((b * H_ + y) * W_ + x0) * (C_ * 4);
    #pragma unroll
    for (int sub = 0; sub < 3; sub++) {                 // 768 = 3*256
        const int chi = sub * 256 + tid;                // ch*4 + i
        const bool msk = (chi & 3) == 3;                // i == 3 -> mask z,w
        const float* row = &s[chi * PITCH];

        float w[PITCH], wm[PITCH];
        #pragma unroll
        for (int c = 0; c < PITCH; c++) w[c] = row[c];
        #pragma unroll
        for (int c = 0; c < PITCH; c++) wm[c] = msk ? 0.f : w[c];

        float4* o = obase + chi;
        #pragma unroll
        for (int xl = 0; xl < TX; xl++) {
            __stcs(o + xl * (C_ * 4),
                   make_float4(w[xl], w[xl + 1], wm[xl + 2], wm[xl + 3]));
        }
    }
}

extern "C" void kernel_launch(void* const* d_in, const int* in_sizes, int n_in,
                              void* d_out, int out_size)
{
    const float* in  = (const float*)d_in[0];
    float4*      out = (float4*)d_out;

    const int blocks = B_ * H_ * XT;   // 2304
    block_sample_smem<<<blocks, 256>>>(in, out);
}